// round 14
// baseline (speedup 1.0000x reference)
#include <cuda_runtime.h>
#include <cstdint>

// x:     (128, 9, 84, 420) fp32
// shift: (128, 2) int32, values in [0, 8]
// out[n,c,i,j] = x[n,c, yy, xx]
//   yy = max(ky + i - 4, 0) % 84      (upper clamp never binds; range [-4,87])
//   xx = clamp(kx + j - 4, 0, 419)

#define N_   128
#define C_   9
#define H_   84
#define W_   420
#define W4_  (W_ / 4)                 // 105 float4 per row
#define ROWS (N_ * C_ * H_)           // 96768

#define JS    3                       // j-slices per thread (R12 optimum)
#define J_OFF (W4_ / JS)              // 35 float4 stride within the row
#define T3    (ROWS * J_OFF)          // 3,386,880 threads

// min-blocks=7 caps regs at 36 (65536/(7*256)) -> 56 warps/SM theoretical
__global__ void __launch_bounds__(256, 7)
random_shifts_kernel(const float* __restrict__ x,
                     const int*   __restrict__ shift,
                     float*       __restrict__ out)
{
    int t = blockIdx.x * blockDim.x + threadIdx.x;
    if (t >= T3) return;

    int j4  = t % J_OFF;        // base j4 in [0, 35)
    int row = t / J_OFF;        // (n*C + c)*H + i
    int i   = row % H_;
    int nc  = row / H_;
    int n   = nc / C_;

    int kx = __ldg(&shift[2 * n + 0]);
    int ky = __ldg(&shift[2 * n + 1]);

    // vertical index: clamp at 0, then wrap (tile) at 84 — shared by all 3 outputs
    int yy = ky + i - 4;
    yy = max(yy, 0);
    if (yy >= H_) yy -= H_;

    const float*  src  = x + ((size_t)nc * H_ + yy) * W_;
    const float4* src4 = reinterpret_cast<const float4*>(src);
    int r = kx & 3;             // misalignment — uniform per image

    // Per-output unclamped base columns
    int b0 = kx + (j4            ) * 4 - 4;
    int b1 = kx + (j4 +     J_OFF) * 4 - 4;
    int b2 = kx + (j4 + 2 * J_OFF) * 4 - 4;

    bool f0 = (b0 >= 0) && (b0 <= W_ - 8);
    bool f1 = (b1 >= 0) && (b1 <= W_ - 8);
    bool f2 = (b2 >= 0) && (b2 <= W_ - 8);

    // Front-batched loads: 6 independent LDG.128
    float4 A0, B0, A1, B1, A2, B2;
    if (f0) { int q = b0 >> 2; A0 = __ldg(src4 + q); B0 = __ldg(src4 + q + 1); }
    if (f1) { int q = b1 >> 2; A1 = __ldg(src4 + q); B1 = __ldg(src4 + q + 1); }
    if (f2) { int q = b2 >> 2; A2 = __ldg(src4 + q); B2 = __ldg(src4 + q + 1); }

    float4 v0, v1, v2;

#define SELECT(v, A, B)                                                       \
    v.x = (r == 0) ? A.x : (r == 1) ? A.y : (r == 2) ? A.z : A.w;             \
    v.y = (r == 0) ? A.y : (r == 1) ? A.z : (r == 2) ? A.w : B.x;             \
    v.z = (r == 0) ? A.z : (r == 1) ? A.w : (r == 2) ? B.x : B.y;             \
    v.w = (r == 0) ? A.w : (r == 1) ? B.x : (r == 2) ? B.y : B.z;

#define EDGE(v, bb)                                                           \
    {                                                                         \
        int e0 = min(max(bb + 0, 0), W_ - 1);                                 \
        int e1 = min(max(bb + 1, 0), W_ - 1);                                 \
        int e2 = min(max(bb + 2, 0), W_ - 1);                                 \
        int e3 = min(max(bb + 3, 0), W_ - 1);                                 \
        v.x = __ldg(src + e0); v.y = __ldg(src + e1);                         \
        v.z = __ldg(src + e2); v.w = __ldg(src + e3);                         \
    }

    if (f0) { SELECT(v0, A0, B0) } else EDGE(v0, b0)
    if (f1) { SELECT(v1, A1, B1) } else EDGE(v1, b1)
    if (f2) { SELECT(v2, A2, B2) } else EDGE(v2, b2)

    // Coalesced streaming stores: three contiguous 560B-stride runs per warp
    float4* out4 = reinterpret_cast<float4*>(out) + (size_t)row * W4_ + j4;
    __stcs(out4,             v0);
    __stcs(out4 +     J_OFF, v1);
    __stcs(out4 + 2 * J_OFF, v2);
}

extern "C" void kernel_launch(void* const* d_in, const int* in_sizes, int n_in,
                              void* d_out, int out_size)
{
    const float* x     = (const float*)d_in[0];
    const int*   shift = (const int*)d_in[1];
    float*       out   = (float*)d_out;

    const int threads = 256;
    const int blocks  = (T3 + threads - 1) / threads;
    random_shifts_kernel<<<blocks, threads>>>(x, shift, out);
}

// round 15
// speedup vs baseline: 1.4762x; 1.4762x over previous
#include <cuda_runtime.h>
#include <cstdint>

// x:     (128, 9, 84, 420) fp32
// shift: (128, 2) int32, values in [0, 8]
// out[n,c,i,j] = x[n,c, yy, xx]
//   yy = max(ky + i - 4, 0) % 84      (upper clamp never binds; range [-4,87])
//   xx = clamp(kx + j - 4, 0, 419)

#define N_   128
#define C_   9
#define H_   84
#define W_   420
#define W4_  (W_ / 4)                 // 105 float4 per row
#define ROWS (N_ * C_ * H_)           // 96768

#define JS    3                       // j-slices per thread (R12 optimum)
#define J_OFF (W4_ / JS)              // 35 float4 stride within the row
#define T3    (ROWS * J_OFF)          // 3,386,880 threads

// NOTE: no min-blocks clause — R14 proved forcing regs below 39 spills.
__global__ void __launch_bounds__(128)
random_shifts_kernel(const float* __restrict__ x,
                     const int*   __restrict__ shift,
                     float*       __restrict__ out)
{
    int t = blockIdx.x * blockDim.x + threadIdx.x;
    if (t >= T3) return;

    int j4  = t % J_OFF;        // base j4 in [0, 35)
    int row = t / J_OFF;        // (n*C + c)*H + i
    int i   = row % H_;
    int nc  = row / H_;
    int n   = nc / C_;

    int kx = __ldg(&shift[2 * n + 0]);
    int ky = __ldg(&shift[2 * n + 1]);

    // vertical index: clamp at 0, then wrap (tile) at 84 — shared by all 3 outputs
    int yy = ky + i - 4;
    yy = max(yy, 0);
    if (yy >= H_) yy -= H_;

    const float*  src  = x + ((size_t)nc * H_ + yy) * W_;
    const float4* src4 = reinterpret_cast<const float4*>(src);
    int r = kx & 3;             // misalignment — uniform per image

    // Per-output unclamped base columns
    int b0 = kx + (j4            ) * 4 - 4;
    int b1 = kx + (j4 +     J_OFF) * 4 - 4;
    int b2 = kx + (j4 + 2 * J_OFF) * 4 - 4;

    bool f0 = (b0 >= 0) && (b0 <= W_ - 8);
    bool f1 = (b1 >= 0) && (b1 <= W_ - 8);
    bool f2 = (b2 >= 0) && (b2 <= W_ - 8);

    // Front-batched loads: 6 independent LDG.128
    float4 A0, B0, A1, B1, A2, B2;
    if (f0) { int q = b0 >> 2; A0 = __ldg(src4 + q); B0 = __ldg(src4 + q + 1); }
    if (f1) { int q = b1 >> 2; A1 = __ldg(src4 + q); B1 = __ldg(src4 + q + 1); }
    if (f2) { int q = b2 >> 2; A2 = __ldg(src4 + q); B2 = __ldg(src4 + q + 1); }

    float4 v0, v1, v2;

#define SELECT(v, A, B)                                                       \
    v.x = (r == 0) ? A.x : (r == 1) ? A.y : (r == 2) ? A.z : A.w;             \
    v.y = (r == 0) ? A.y : (r == 1) ? A.z : (r == 2) ? A.w : B.x;             \
    v.z = (r == 0) ? A.z : (r == 1) ? A.w : (r == 2) ? B.x : B.y;             \
    v.w = (r == 0) ? A.w : (r == 1) ? B.x : (r == 2) ? B.y : B.z;

#define EDGE(v, bb)                                                           \
    {                                                                         \
        int e0 = min(max(bb + 0, 0), W_ - 1);                                 \
        int e1 = min(max(bb + 1, 0), W_ - 1);                                 \
        int e2 = min(max(bb + 2, 0), W_ - 1);                                 \
        int e3 = min(max(bb + 3, 0), W_ - 1);                                 \
        v.x = __ldg(src + e0); v.y = __ldg(src + e1);                         \
        v.z = __ldg(src + e2); v.w = __ldg(src + e3);                         \
    }

    if (f0) { SELECT(v0, A0, B0) } else EDGE(v0, b0)
    if (f1) { SELECT(v1, A1, B1) } else EDGE(v1, b1)
    if (f2) { SELECT(v2, A2, B2) } else EDGE(v2, b2)

    // Coalesced streaming stores
    float4* out4 = reinterpret_cast<float4*>(out) + (size_t)row * W4_ + j4;
    __stcs(out4,             v0);
    __stcs(out4 +     J_OFF, v1);
    __stcs(out4 + 2 * J_OFF, v2);
}

extern "C" void kernel_launch(void* const* d_in, const int* in_sizes, int n_in,
                              void* d_out, int out_size)
{
    const float* x     = (const float*)d_in[0];
    const int*   shift = (const int*)d_in[1];
    float*       out   = (float*)d_out;

    const int threads = 128;
    const int blocks  = (T3 + threads - 1) / threads;
    random_shifts_kernel<<<blocks, threads>>>(x, shift, out);
}